// round 15
// baseline (speedup 1.0000x reference)
#include <cuda_runtime.h>
#include <cuda_fp16.h>
#include <math.h>
#include <stdint.h>

#define T_TOK 1024
#define HDIM  2048
#define NEXP  16
#define IDIM  1408
#define GU2   2816
#define SIDIM 2816
#define SGU2  5632
#define TOPK  4

// GEMM tiling
#define BM 128
#define BN 128
#define BK 32          // halves per k-tile (64B of data per row)
#define ROWB 80        // padded smem row bytes
#define STG  20480     // per-stage bytes: A 128*80 + B 128*80
#define SMEMT_G (2 * STG + 512)

// ---------------- device scratch ----------------
__device__ int   g_count[NEXP];
__device__ int   g_list[NEXP * T_TOK];
__device__ float g_topw[T_TOK * TOPK];
__device__ __half g_xh[(size_t)T_TOK * HDIM];
__device__ __half g_wguh[(size_t)NEXP * GU2 * HDIM];
__device__ __half g_wdnh[(size_t)NEXP * HDIM * IDIM];
__device__ __half g_sguh[(size_t)SGU2 * HDIM];
__device__ __half g_sdnh[(size_t)HDIM * SIDIM];
__device__ __half g_guh[(size_t)NEXP * T_TOK * GU2];   // raw routed GU out
__device__ __half g_acr[(size_t)NEXP * T_TOK * IDIM];  // routed act
__device__ __half g_gush[(size_t)T_TOK * SGU2];        // raw shared GU out
__device__ __half g_acs[(size_t)T_TOK * SIDIM];        // shared act
__device__ float  g_ds[(size_t)T_TOK * TOPK * HDIM];   // weighted routed down

// ---------------- helpers ----------------
__device__ __forceinline__ uint32_t smem_u32(const void* p) {
    uint32_t a;
    asm("{ .reg .u64 t; cvta.to.shared.u64 t, %1; cvt.u32.u64 %0, t; }" : "=r"(a) : "l"(p));
    return a;
}
__device__ __forceinline__ void cpa16(uint32_t dst, const void* src) {
    asm volatile("cp.async.cg.shared.global [%0], [%1], 16;" :: "r"(dst), "l"(src));
}
#define CP_COMMIT() asm volatile("cp.async.commit_group;" ::: "memory")
#define CP_WAIT(n)  asm volatile("cp.async.wait_group %0;" :: "n"(n) : "memory")

__device__ __forceinline__ uint32_t lds32(uint32_t a) {
    uint32_t v;
    asm volatile("ld.shared.b32 %0, [%1];" : "=r"(v) : "r"(a));
    return v;
}
__device__ __forceinline__ void mma16(float* c, const uint32_t* a, uint32_t b0, uint32_t b1) {
    asm volatile(
        "mma.sync.aligned.m16n8k16.row.col.f32.f16.f16.f32 "
        "{%0,%1,%2,%3}, {%4,%5,%6,%7}, {%8,%9}, {%0,%1,%2,%3};\n"
        : "+f"(c[0]), "+f"(c[1]), "+f"(c[2]), "+f"(c[3])
        : "r"(a[0]), "r"(a[1]), "r"(a[2]), "r"(a[3]), "r"(b0), "r"(b1));
}

__device__ __forceinline__ float silu_f(float g) { return g / (1.f + __expf(-g)); }

// ---------------- conversion ----------------
// IMPORTANT: destination selected BY NAME in device code (a __device__ array
// symbol passed as a kernel argument from host is a bogus pointer).
template<int ID>
__global__ __launch_bounds__(256) void cvt_kernel(const float* __restrict__ s, int n8) {
    __half* d;
    if (ID == 0) d = g_xh;
    else if (ID == 1) d = g_wguh;
    else if (ID == 2) d = g_wdnh;
    else if (ID == 3) d = g_sguh;
    else d = g_sdnh;

    int i = blockIdx.x * 256 + threadIdx.x;
    if (i >= n8) return;
    const float4* sp = (const float4*)s + (size_t)i * 2;
    float4 v0 = sp[0], v1 = sp[1];
    __half2 h[4];
    h[0] = __floats2half2_rn(v0.x, v0.y);
    h[1] = __floats2half2_rn(v0.z, v0.w);
    h[2] = __floats2half2_rn(v1.x, v1.y);
    h[3] = __floats2half2_rn(v1.z, v1.w);
    *(uint4*)(d + (size_t)i * 8) = *(uint4*)h;
}

// ---------------- router ----------------
__global__ void zero_counts_kernel() {
    if (threadIdx.x < NEXP) g_count[threadIdx.x] = 0;
}
__global__ __launch_bounds__(128) void router_kernel(const float* __restrict__ x,
                                                     const float* __restrict__ gw) {
    const int t = blockIdx.x;
    const int tid = threadIdx.x;
    const int e = tid & 15;
    const int lane = tid >> 4;
    const float* xr = x + (size_t)t * HDIM;
    const float* wr = gw + (size_t)e * HDIM;
    float p = 0.f;
    for (int h = lane; h < HDIM; h += 8) p += xr[h] * wr[h];
    __shared__ float red[16][8];
    red[e][lane] = p;
    __syncthreads();
    if (tid < 16) {
        float s = 0.f;
        #pragma unroll
        for (int j = 0; j < 8; j++) s += red[tid][j];
        red[tid][0] = s;
    }
    __syncthreads();
    if (tid == 0) {
        float lg[16], pr[16];
        float mx = -1e30f;
        #pragma unroll
        for (int i = 0; i < 16; i++) { lg[i] = red[i][0]; mx = fmaxf(mx, lg[i]); }
        float sum = 0.f;
        #pragma unroll
        for (int i = 0; i < 16; i++) { pr[i] = expf(lg[i] - mx); sum += pr[i]; }
        #pragma unroll
        for (int i = 0; i < 16; i++) pr[i] /= sum;
        int used = 0;
        int idx[TOPK]; float wv[TOPK]; float wsum = 0.f;
        #pragma unroll
        for (int k = 0; k < TOPK; k++) {
            float best = -1.f; int bi = 0;
            #pragma unroll
            for (int i = 0; i < 16; i++)
                if (!((used >> i) & 1) && pr[i] > best) { best = pr[i]; bi = i; }
            used |= (1 << bi);
            idx[k] = bi; wv[k] = best; wsum += best;
        }
        #pragma unroll
        for (int k = 0; k < TOPK; k++) {
            g_topw[t * TOPK + k] = wv[k] / wsum;
            int slot = atomicAdd(&g_count[idx[k]], 1);
            g_list[idx[k] * T_TOK + slot] = t * TOPK + k;
        }
    }
}

// =====================================================================
// fp16 HMMA GEMM 128x128x32, 4 warps (64x64 warp tiles), double buffer
// MODE 0: routed GU   A=g_xh(gather)  B=g_wguh[e]  C=g_guh[e]  K=2048
// MODE 1: routed DOWN A=g_acr[e]      B=g_wdnh[e]  C=g_ds scat K=1408
// MODE 2: shared GU   A=g_xh          B=g_sguh     C=g_gush    K=2048
// MODE 3: shared DOWN A=g_acs         B=g_sdnh     C=out+comb  K=2816
// =====================================================================
template<int MODE>
__global__ void __launch_bounds__(128) gemm_h(float* __restrict__ Cext) {
    constexpr int KD = (MODE == 1) ? IDIM : (MODE == 3) ? SIDIM : HDIM;
    constexpr int KT = KD / BK;
    constexpr bool CNT = (MODE <= 1);

    extern __shared__ __align__(128) char smx[];
    const int tid = threadIdx.x;
    const int e = blockIdx.z;
    const int cnt = CNT ? g_count[e] : T_TOK;
    const int m0 = blockIdx.x * BM;
    if (m0 >= cnt) return;
    const int n0 = blockIdx.y * BN;

    const uint32_t sb = smem_u32(smx);
    int* rowsm = (int*)(smx + 2 * STG);

    if (CNT) {
        int r = m0 + tid;
        if (r >= cnt) r = cnt - 1;
        rowsm[tid] = g_list[e * T_TOK + r];
        __syncthreads();
    }

    // -------- staging sources (thread tid owns row tid of A and of B) --------
    const __half* aSrc;
    if (MODE == 0)      aSrc = g_xh + (size_t)(rowsm[tid] >> 2) * HDIM;
    else if (MODE == 1) { int r = m0 + tid; if (r >= cnt) r = cnt - 1;
                          aSrc = g_acr + ((size_t)e * T_TOK + r) * IDIM; }
    else if (MODE == 2) aSrc = g_xh + (size_t)(m0 + tid) * HDIM;
    else                aSrc = g_acs + (size_t)(m0 + tid) * SIDIM;

    const __half* bSrc;
    if (MODE == 0)      bSrc = g_wguh + (size_t)e * GU2 * HDIM + (size_t)(n0 + tid) * HDIM;
    else if (MODE == 1) bSrc = g_wdnh + (size_t)e * HDIM * IDIM + (size_t)(n0 + tid) * IDIM;
    else if (MODE == 2) bSrc = g_sguh + (size_t)(n0 + tid) * HDIM;
    else                bSrc = g_sdnh + (size_t)(n0 + tid) * SIDIM;

    const uint32_t aDst = sb + tid * ROWB;
    const uint32_t bDst = sb + 10240 + tid * ROWB;

    const int lane = tid & 31, wid = tid >> 5;
    const int wm = wid & 1, wn = wid >> 1;
    const int g = lane >> 2, t = lane & 3;

    float acc[4][8][4];
    #pragma unroll
    for (int i = 0; i < 4; i++)
        #pragma unroll
        for (int j = 0; j < 8; j++)
            #pragma unroll
            for (int k = 0; k < 4; k++) acc[i][j][k] = 0.f;

    // prologue: stage 0
    #pragma unroll
    for (int c = 0; c < 4; c++) cpa16(aDst + c * 16, aSrc + c * 8);
    #pragma unroll
    for (int c = 0; c < 4; c++) cpa16(bDst + c * 16, bSrc + c * 8);
    CP_COMMIT();

    for (int kt = 0; kt < KT; kt++) {
        // issue next stage, then drain current
        if (kt + 1 < KT) {
            const uint32_t ds = ((kt + 1) & 1) * STG;
            const int ko = (kt + 1) * BK;
            #pragma unroll
            for (int c = 0; c < 4; c++) cpa16(aDst + ds + c * 16, aSrc + ko + c * 8);
            #pragma unroll
            for (int c = 0; c < 4; c++) cpa16(bDst + ds + c * 16, bSrc + ko + c * 8);
            CP_COMMIT();
            CP_WAIT(1);
        } else {
            CP_WAIT(0);
        }
        __syncthreads();

        const uint32_t stg = sb + (kt & 1) * STG;
        #pragma unroll
        for (int ks = 0; ks < 2; ks++) {
            // A fragments: a0 row=g k=2t | a1 row+8 | a2 k+8 | a3 row+8,k+8
            uint32_t a[4][4];
            #pragma unroll
            for (int mi = 0; mi < 4; mi++) {
                const uint32_t base = stg + (uint32_t)((wm * 64 + mi * 16 + g) * ROWB + t * 4 + ks * 32);
                a[mi][0] = lds32(base);
                a[mi][1] = lds32(base + 8 * ROWB);
                a[mi][2] = lds32(base + 16);
                a[mi][3] = lds32(base + 8 * ROWB + 16);
            }
            #pragma unroll
            for (int ni = 0; ni < 8; ni++) {
                const uint32_t bb = stg + (uint32_t)(10240 + (wn * 64 + ni * 8 + g) * ROWB + t * 4 + ks * 32);
                const uint32_t b0 = lds32(bb);
                const uint32_t b1 = lds32(bb + 16);
                #pragma unroll
                for (int mi = 0; mi < 4; mi++)
                    mma16(acc[mi][ni], a[mi], b0, b1);
            }
        }
        __syncthreads();
    }

    // -------- epilogue --------
    const int colb = n0 + wn * 64 + t * 2;
    #pragma unroll
    for (int mi = 0; mi < 4; mi++) {
        #pragma unroll
        for (int hh = 0; hh < 2; hh++) {
            const int rloc = wm * 64 + mi * 16 + g + hh * 8;
            const int gr = m0 + rloc;
            if (CNT && gr >= cnt) continue;
            if (MODE == 0) {
                __half* cp = g_guh + ((size_t)e * T_TOK + gr) * GU2 + colb;
                #pragma unroll
                for (int ni = 0; ni < 8; ni++)
                    *(__half2*)(cp + ni * 8) =
                        __floats2half2_rn(acc[mi][ni][hh * 2], acc[mi][ni][hh * 2 + 1]);
            } else if (MODE == 1) {
                const int a = rowsm[rloc];
                const float w = g_topw[a];
                float* cp = g_ds + (size_t)a * HDIM + colb;
                #pragma unroll
                for (int ni = 0; ni < 8; ni++)
                    *(float2*)(cp + ni * 8) = make_float2(acc[mi][ni][hh * 2] * w,
                                                          acc[mi][ni][hh * 2 + 1] * w);
            } else if (MODE == 2) {
                __half* cp = g_gush + (size_t)gr * SGU2 + colb;
                #pragma unroll
                for (int ni = 0; ni < 8; ni++)
                    *(__half2*)(cp + ni * 8) =
                        __floats2half2_rn(acc[mi][ni][hh * 2], acc[mi][ni][hh * 2 + 1]);
            } else {
                float* cp = Cext + (size_t)gr * HDIM + colb;
                const float* ds = g_ds + (size_t)gr * TOPK * HDIM + colb;
                #pragma unroll
                for (int ni = 0; ni < 8; ni++) {
                    float s0 = acc[mi][ni][hh * 2];
                    float s1 = acc[mi][ni][hh * 2 + 1];
                    #pragma unroll
                    for (int k = 0; k < TOPK; k++) {
                        float2 d = *(const float2*)(ds + (size_t)k * HDIM + ni * 8);
                        s0 += d.x; s1 += d.y;
                    }
                    *(float2*)(cp + ni * 8) = make_float2(s0, s1);
                }
            }
        }
    }
}

// ---------------- activation kernels (fp16 in/out, fp32 math) ----------------
__global__ __launch_bounds__(256) void act_routed_kernel() {
    const int e = blockIdx.y;
    const int cnt = g_count[e];
    const int slot = blockIdx.x * 2 + (threadIdx.x >> 7);
    if (slot >= cnt) return;
    const uint4* gp = (const uint4*)(g_guh + ((size_t)e * T_TOK + slot) * GU2);
    const uint4* up = (const uint4*)(g_guh + ((size_t)e * T_TOK + slot) * GU2 + IDIM);
    uint4* op = (uint4*)(g_acr + ((size_t)e * T_TOK + slot) * IDIM);
    for (int c = (threadIdx.x & 127); c < IDIM / 8; c += 128) {
        uint4 gv = gp[c], uv = up[c], ov;
        const __half2* g2 = (const __half2*)&gv;
        const __half2* u2 = (const __half2*)&uv;
        __half2* o2 = (__half2*)&ov;
        #pragma unroll
        for (int j = 0; j < 4; j++) {
            float2 gf = __half22float2(g2[j]);
            float2 uf = __half22float2(u2[j]);
            o2[j] = __floats2half2_rn(silu_f(gf.x) * uf.x, silu_f(gf.y) * uf.y);
        }
        op[c] = ov;
    }
}
__global__ __launch_bounds__(256) void act_shared_kernel() {
    const int r = blockIdx.x;
    const uint4* gp = (const uint4*)(g_gush + (size_t)r * SGU2);
    const uint4* up = (const uint4*)(g_gush + (size_t)r * SGU2 + SIDIM);
    uint4* op = (uint4*)(g_acs + (size_t)r * SIDIM);
    for (int c = threadIdx.x; c < SIDIM / 8; c += 256) {
        uint4 gv = gp[c], uv = up[c], ov;
        const __half2* g2 = (const __half2*)&gv;
        const __half2* u2 = (const __half2*)&uv;
        __half2* o2 = (__half2*)&ov;
        #pragma unroll
        for (int j = 0; j < 4; j++) {
            float2 gf = __half22float2(g2[j]);
            float2 uf = __half22float2(u2[j]);
            o2[j] = __floats2half2_rn(silu_f(gf.x) * uf.x, silu_f(gf.y) * uf.y);
        }
        op[c] = ov;
    }
}

// ---------------- launch ----------------
extern "C" void kernel_launch(void* const* d_in, const int* in_sizes, int n_in,
                              void* d_out, int out_size) {
    const float* x     = (const float*)d_in[0];
    const float* gw    = (const float*)d_in[1];
    const float* wgu   = (const float*)d_in[2];
    const float* wdown = (const float*)d_in[3];
    const float* sgu   = (const float*)d_in[4];
    const float* sdown = (const float*)d_in[5];
    float* out = (float*)d_out;

    cudaFuncSetAttribute(gemm_h<0>, cudaFuncAttributeMaxDynamicSharedMemorySize, SMEMT_G);
    cudaFuncSetAttribute(gemm_h<1>, cudaFuncAttributeMaxDynamicSharedMemorySize, SMEMT_G);
    cudaFuncSetAttribute(gemm_h<2>, cudaFuncAttributeMaxDynamicSharedMemorySize, SMEMT_G);
    cudaFuncSetAttribute(gemm_h<3>, cudaFuncAttributeMaxDynamicSharedMemorySize, SMEMT_G);

    zero_counts_kernel<<<1, 32>>>();
    router_kernel<<<T_TOK, 128>>>(x, gw);

    // fp16 conversions (dst selected by template ID inside device code)
    {
        int n8;
        n8 = (int)((size_t)T_TOK * HDIM / 8);
        cvt_kernel<0><<<(n8 + 255) / 256, 256>>>(x, n8);
        n8 = (int)((size_t)NEXP * GU2 * HDIM / 8);
        cvt_kernel<1><<<(n8 + 255) / 256, 256>>>(wgu, n8);
        n8 = (int)((size_t)NEXP * HDIM * IDIM / 8);
        cvt_kernel<2><<<(n8 + 255) / 256, 256>>>(wdown, n8);
        n8 = (int)((size_t)SGU2 * HDIM / 8);
        cvt_kernel<3><<<(n8 + 255) / 256, 256>>>(sgu, n8);
        n8 = (int)((size_t)HDIM * SIDIM / 8);
        cvt_kernel<4><<<(n8 + 255) / 256, 256>>>(sdown, n8);
    }

    // GU GEMMs
    gemm_h<0><<<dim3(T_TOK / BM, GU2 / BN, NEXP), 128, SMEMT_G>>>(nullptr);
    gemm_h<2><<<dim3(T_TOK / BM, SGU2 / BN, 1),   128, SMEMT_G>>>(nullptr);
    // activations
    act_routed_kernel<<<dim3(512, NEXP), 256>>>();
    act_shared_kernel<<<T_TOK, 256>>>();
    // DOWN GEMMs
    gemm_h<1><<<dim3(T_TOK / BM, HDIM / BN, NEXP), 128, SMEMT_G>>>(nullptr);
    gemm_h<3><<<dim3(T_TOK / BM, HDIM / BN, 1),    128, SMEMT_G>>>(out);
}

// round 17
// speedup vs baseline: 1.0840x; 1.0840x over previous
#include <cuda_runtime.h>
#include <cuda_fp16.h>
#include <math.h>
#include <stdint.h>

#define T_TOK 1024
#define HDIM  2048
#define NEXP  16
#define IDIM  1408
#define GU2   2816
#define SIDIM 2816
#define SGU2  5632
#define TOPK  4

// GEMM tiling
#define BM 128
#define BN 128
#define BK 32          // halves per k-tile (64B of data per row)
#define ROWB 80        // padded smem row bytes
#define STG  20480     // per-stage bytes: A 128*80 + B 128*80
#define SMEMT_G (2 * STG + 512)

// ---------------- device scratch ----------------
__device__ int   g_count[NEXP];
__device__ int   g_list[NEXP * T_TOK];
__device__ float g_topw[T_TOK * TOPK];
__device__ __half g_xh[(size_t)T_TOK * HDIM];
__device__ __half g_wguh[(size_t)NEXP * GU2 * HDIM];
__device__ __half g_wdnh[(size_t)NEXP * HDIM * IDIM];
__device__ __half g_sguh[(size_t)SGU2 * HDIM];
__device__ __half g_sdnh[(size_t)HDIM * SIDIM];
__device__ __half g_guh[(size_t)NEXP * T_TOK * GU2];   // raw routed GU out
__device__ __half g_acr[(size_t)NEXP * T_TOK * IDIM];  // routed act
__device__ __half g_gush[(size_t)T_TOK * SGU2];        // raw shared GU out
__device__ __half g_acs[(size_t)T_TOK * SIDIM];        // shared act
__device__ float  g_ds[(size_t)T_TOK * TOPK * HDIM];   // weighted routed down

// ---------------- helpers ----------------
__device__ __forceinline__ uint32_t smem_u32(const void* p) {
    uint32_t a;
    asm("{ .reg .u64 t; cvta.to.shared.u64 t, %1; cvt.u32.u64 %0, t; }" : "=r"(a) : "l"(p));
    return a;
}
__device__ __forceinline__ void cpa16(uint32_t dst, const void* src) {
    asm volatile("cp.async.cg.shared.global [%0], [%1], 16;" :: "r"(dst), "l"(src));
}
#define CP_COMMIT() asm volatile("cp.async.commit_group;" ::: "memory")
#define CP_WAIT(n)  asm volatile("cp.async.wait_group %0;" :: "n"(n) : "memory")

#define LDSMX4(r0, r1, r2, r3, addr) \
    asm volatile("ldmatrix.sync.aligned.m8n8.x4.shared.b16 {%0,%1,%2,%3}, [%4];" \
        : "=r"(r0), "=r"(r1), "=r"(r2), "=r"(r3) : "r"(addr))

__device__ __forceinline__ void mma16(float* c, const uint32_t* a, uint32_t b0, uint32_t b1) {
    asm volatile(
        "mma.sync.aligned.m16n8k16.row.col.f32.f16.f16.f32 "
        "{%0,%1,%2,%3}, {%4,%5,%6,%7}, {%8,%9}, {%0,%1,%2,%3};\n"
        : "+f"(c[0]), "+f"(c[1]), "+f"(c[2]), "+f"(c[3])
        : "r"(a[0]), "r"(a[1]), "r"(a[2]), "r"(a[3]), "r"(b0), "r"(b1));
}

__device__ __forceinline__ float silu_f(float g) { return g / (1.f + __expf(-g)); }

// ---------------- conversion (dst selected BY NAME in device code) ----------------
template<int ID>
__global__ __launch_bounds__(256) void cvt_kernel(const float* __restrict__ s, int n8) {
    __half* d;
    if (ID == 0) d = g_xh;
    else if (ID == 1) d = g_wguh;
    else if (ID == 2) d = g_wdnh;
    else if (ID == 3) d = g_sguh;
    else d = g_sdnh;

    int i = blockIdx.x * 256 + threadIdx.x;
    if (i >= n8) return;
    const float4* sp = (const float4*)s + (size_t)i * 2;
    float4 v0 = sp[0], v1 = sp[1];
    __half2 h[4];
    h[0] = __floats2half2_rn(v0.x, v0.y);
    h[1] = __floats2half2_rn(v0.z, v0.w);
    h[2] = __floats2half2_rn(v1.x, v1.y);
    h[3] = __floats2half2_rn(v1.z, v1.w);
    *(uint4*)(d + (size_t)i * 8) = *(uint4*)h;
}

// ---------------- router ----------------
__global__ void zero_counts_kernel() {
    if (threadIdx.x < NEXP) g_count[threadIdx.x] = 0;
}
__global__ __launch_bounds__(128) void router_kernel(const float* __restrict__ x,
                                                     const float* __restrict__ gw) {
    const int t = blockIdx.x;
    const int tid = threadIdx.x;
    const int e = tid & 15;
    const int lane = tid >> 4;
    const float* xr = x + (size_t)t * HDIM;
    const float* wr = gw + (size_t)e * HDIM;
    float p = 0.f;
    for (int h = lane; h < HDIM; h += 8) p += xr[h] * wr[h];
    __shared__ float red[16][8];
    red[e][lane] = p;
    __syncthreads();
    if (tid < 16) {
        float s = 0.f;
        #pragma unroll
        for (int j = 0; j < 8; j++) s += red[tid][j];
        red[tid][0] = s;
    }
    __syncthreads();
    if (tid == 0) {
        float lg[16], pr[16];
        float mx = -1e30f;
        #pragma unroll
        for (int i = 0; i < 16; i++) { lg[i] = red[i][0]; mx = fmaxf(mx, lg[i]); }
        float sum = 0.f;
        #pragma unroll
        for (int i = 0; i < 16; i++) { pr[i] = expf(lg[i] - mx); sum += pr[i]; }
        #pragma unroll
        for (int i = 0; i < 16; i++) pr[i] /= sum;
        int used = 0;
        int idx[TOPK]; float wv[TOPK]; float wsum = 0.f;
        #pragma unroll
        for (int k = 0; k < TOPK; k++) {
            float best = -1.f; int bi = 0;
            #pragma unroll
            for (int i = 0; i < 16; i++)
                if (!((used >> i) & 1) && pr[i] > best) { best = pr[i]; bi = i; }
            used |= (1 << bi);
            idx[k] = bi; wv[k] = best; wsum += best;
        }
        #pragma unroll
        for (int k = 0; k < TOPK; k++) {
            g_topw[t * TOPK + k] = wv[k] / wsum;
            int slot = atomicAdd(&g_count[idx[k]], 1);
            g_list[idx[k] * T_TOK + slot] = t * TOPK + k;
        }
    }
}

// =====================================================================
// fp16 HMMA GEMM 128x128xK, 4 warps (64x64 warp tiles), double buffer,
// ldmatrix fragment loads.
// PHASE 0 (GU):   z<16: routed GU expert z (gather, cnt) | z==16: shared GU
// PHASE 1 (DOWN): z<16: routed DOWN expert z (scatter)   | z==16: shared DOWN
// =====================================================================
template<int PHASE>
__global__ void __launch_bounds__(128) gemm_m(float* __restrict__ Cext) {
    extern __shared__ __align__(128) char smx[];
    const int tid = threadIdx.x;
    const int z = blockIdx.z;
    const bool routed = (z < NEXP);
    const int e = routed ? z : 0;
    const int cnt = routed ? g_count[e] : T_TOK;
    const int m0 = blockIdx.x * BM;
    if (m0 >= cnt) return;
    const int n0 = blockIdx.y * BN;
    if (PHASE == 0 && routed && n0 >= GU2) return;

    const int KD = (PHASE == 0) ? HDIM : (routed ? IDIM : SIDIM);
    const int KT = KD / BK;

    const uint32_t sb = smem_u32(smx);
    int* rowsm = (int*)(smx + 2 * STG);

    if (routed) {
        int r = m0 + tid;
        if (r >= cnt) r = cnt - 1;
        rowsm[tid] = g_list[e * T_TOK + r];
        __syncthreads();
    }

    // -------- staging sources (thread tid owns row tid of A and of B) --------
    const __half* aSrc;
    if (PHASE == 0) {
        aSrc = routed ? (g_xh + (size_t)(rowsm[tid] >> 2) * HDIM)
                      : (g_xh + (size_t)(m0 + tid) * HDIM);
    } else {
        if (routed) {
            int r = m0 + tid; if (r >= cnt) r = cnt - 1;
            aSrc = g_acr + ((size_t)e * T_TOK + r) * IDIM;
        } else {
            aSrc = g_acs + (size_t)(m0 + tid) * SIDIM;
        }
    }
    const __half* bSrc;
    if (PHASE == 0) {
        bSrc = routed ? (g_wguh + (size_t)e * GU2 * HDIM + (size_t)(n0 + tid) * HDIM)
                      : (g_sguh + (size_t)(n0 + tid) * HDIM);
    } else {
        bSrc = routed ? (g_wdnh + (size_t)e * HDIM * IDIM + (size_t)(n0 + tid) * IDIM)
                      : (g_sdnh + (size_t)(n0 + tid) * SIDIM);
    }

    const uint32_t aDst = sb + tid * ROWB;
    const uint32_t bDst = sb + 10240 + tid * ROWB;

    const int lane = tid & 31, wid = tid >> 5;
    const int wm = wid & 1, wn = wid >> 1;
    const int g = lane >> 2, t = lane & 3;
    const int jr = lane >> 3, rr = lane & 7;

    // ldmatrix per-lane addresses (byte offsets within a stage)
    // A x4 -> {a0: rows0-7 k0-7, a1: rows8-15 k0-7, a2: rows0-7 k8-15, a3: rows8-15 k8-15}
    uint32_t aOff[4];
    #pragma unroll
    for (int mi = 0; mi < 4; mi++)
        aOff[mi] = (uint32_t)((wm * 64 + mi * 16 + ((jr & 1) << 3) + rr) * ROWB + ((jr >> 1) << 4));
    // B x4 -> {b0(n-block 2q), b1(2q), b0(2q+1), b1(2q+1)}
    uint32_t bOff[4];
    #pragma unroll
    for (int q = 0; q < 4; q++)
        bOff[q] = (uint32_t)(10240 + (wn * 64 + ((2 * q + (jr >> 1)) << 3) + rr) * ROWB + ((jr & 1) << 4));

    float acc[4][8][4];
    #pragma unroll
    for (int i = 0; i < 4; i++)
        #pragma unroll
        for (int j = 0; j < 8; j++)
            #pragma unroll
            for (int k = 0; k < 4; k++) acc[i][j][k] = 0.f;

    // prologue: stage 0
    #pragma unroll
    for (int c = 0; c < 4; c++) cpa16(aDst + c * 16, aSrc + c * 8);
    #pragma unroll
    for (int c = 0; c < 4; c++) cpa16(bDst + c * 16, bSrc + c * 8);
    CP_COMMIT();

    for (int kt = 0; kt < KT; kt++) {
        if (kt + 1 < KT) {
            const uint32_t ds = ((kt + 1) & 1) * STG;
            const int ko = (kt + 1) * BK;
            #pragma unroll
            for (int c = 0; c < 4; c++) cpa16(aDst + ds + c * 16, aSrc + ko + c * 8);
            #pragma unroll
            for (int c = 0; c < 4; c++) cpa16(bDst + ds + c * 16, bSrc + ko + c * 8);
            CP_COMMIT();
            CP_WAIT(1);
        } else {
            CP_WAIT(0);
        }
        __syncthreads();

        const uint32_t stg = sb + (kt & 1) * STG;
        #pragma unroll
        for (int ks = 0; ks < 2; ks++) {
            uint32_t a[4][4], bq[4][4];
            #pragma unroll
            for (int mi = 0; mi < 4; mi++)
                LDSMX4(a[mi][0], a[mi][1], a[mi][2], a[mi][3], stg + aOff[mi] + ks * 32);
            #pragma unroll
            for (int q = 0; q < 4; q++)
                LDSMX4(bq[q][0], bq[q][1], bq[q][2], bq[q][3], stg + bOff[q] + ks * 32);
            #pragma unroll
            for (int mi = 0; mi < 4; mi++)
                #pragma unroll
                for (int ni = 0; ni < 8; ni++)
                    mma16(acc[mi][ni], a[mi], bq[ni >> 1][(ni & 1) * 2], bq[ni >> 1][(ni & 1) * 2 + 1]);
        }
        __syncthreads();
    }

    // -------- epilogue --------
    const int colb = n0 + wn * 64 + t * 2;
    #pragma unroll
    for (int mi = 0; mi < 4; mi++) {
        #pragma unroll
        for (int hh = 0; hh < 2; hh++) {
            const int rloc = wm * 64 + mi * 16 + g + hh * 8;
            const int gr = m0 + rloc;
            if (routed && gr >= cnt) continue;
            if (PHASE == 0) {
                if (routed) {
                    __half* cp = g_guh + ((size_t)e * T_TOK + gr) * GU2 + colb;
                    #pragma unroll
                    for (int ni = 0; ni < 8; ni++)
                        *(__half2*)(cp + ni * 8) =
                            __floats2half2_rn(acc[mi][ni][hh * 2], acc[mi][ni][hh * 2 + 1]);
                } else {
                    __half* cp = g_gush + (size_t)gr * SGU2 + colb;
                    #pragma unroll
                    for (int ni = 0; ni < 8; ni++)
                        *(__half2*)(cp + ni * 8) =
                            __floats2half2_rn(acc[mi][ni][hh * 2], acc[mi][ni][hh * 2 + 1]);
                }
            } else {
                if (routed) {
                    const int a = rowsm[rloc];
                    const float w = g_topw[a];
                    float* cp = g_ds + (size_t)a * HDIM + colb;
                    #pragma unroll
                    for (int ni = 0; ni < 8; ni++)
                        *(float2*)(cp + ni * 8) = make_float2(acc[mi][ni][hh * 2] * w,
                                                              acc[mi][ni][hh * 2 + 1] * w);
                } else {
                    float* cp = Cext + (size_t)gr * HDIM + colb;
                    const float* ds = g_ds + (size_t)gr * TOPK * HDIM + colb;
                    #pragma unroll
                    for (int ni = 0; ni < 8; ni++) {
                        float s0 = acc[mi][ni][hh * 2];
                        float s1 = acc[mi][ni][hh * 2 + 1];
                        #pragma unroll
                        for (int k = 0; k < TOPK; k++) {
                            float2 d = *(const float2*)(ds + (size_t)k * HDIM + ni * 8);
                            s0 += d.x; s1 += d.y;
                        }
                        *(float2*)(cp + ni * 8) = make_float2(s0, s1);
                    }
                }
            }
        }
    }
}

// ---------------- activation kernels ----------------
__global__ __launch_bounds__(256) void act_routed_kernel() {
    const int e = blockIdx.y;
    const int cnt = g_count[e];
    const int slot = blockIdx.x * 2 + (threadIdx.x >> 7);
    if (slot >= cnt) return;
    const uint4* gp = (const uint4*)(g_guh + ((size_t)e * T_TOK + slot) * GU2);
    const uint4* up = (const uint4*)(g_guh + ((size_t)e * T_TOK + slot) * GU2 + IDIM);
    uint4* op = (uint4*)(g_acr + ((size_t)e * T_TOK + slot) * IDIM);
    for (int c = (threadIdx.x & 127); c < IDIM / 8; c += 128) {
        uint4 gv = gp[c], uv = up[c], ov;
        const __half2* g2 = (const __half2*)&gv;
        const __half2* u2 = (const __half2*)&uv;
        __half2* o2 = (__half2*)&ov;
        #pragma unroll
        for (int j = 0; j < 4; j++) {
            float2 gf = __half22float2(g2[j]);
            float2 uf = __half22float2(u2[j]);
            o2[j] = __floats2half2_rn(silu_f(gf.x) * uf.x, silu_f(gf.y) * uf.y);
        }
        op[c] = ov;
    }
}
__global__ __launch_bounds__(256) void act_shared_kernel() {
    const int r = blockIdx.x;
    const uint4* gp = (const uint4*)(g_gush + (size_t)r * SGU2);
    const uint4* up = (const uint4*)(g_gush + (size_t)r * SGU2 + SIDIM);
    uint4* op = (uint4*)(g_acs + (size_t)r * SIDIM);
    for (int c = threadIdx.x; c < SIDIM / 8; c += 256) {
        uint4 gv = gp[c], uv = up[c], ov;
        const __half2* g2 = (const __half2*)&gv;
        const __half2* u2 = (const __half2*)&uv;
        __half2* o2 = (__half2*)&ov;
        #pragma unroll
        for (int j = 0; j < 4; j++) {
            float2 gf = __half22float2(g2[j]);
            float2 uf = __half22float2(u2[j]);
            o2[j] = __floats2half2_rn(silu_f(gf.x) * uf.x, silu_f(gf.y) * uf.y);
        }
        op[c] = ov;
    }
}

// ---------------- launch ----------------
extern "C" void kernel_launch(void* const* d_in, const int* in_sizes, int n_in,
                              void* d_out, int out_size) {
    const float* x     = (const float*)d_in[0];
    const float* gw    = (const float*)d_in[1];
    const float* wgu   = (const float*)d_in[2];
    const float* wdown = (const float*)d_in[3];
    const float* sgu   = (const float*)d_in[4];
    const float* sdown = (const float*)d_in[5];
    float* out = (float*)d_out;

    cudaFuncSetAttribute(gemm_m<0>, cudaFuncAttributeMaxDynamicSharedMemorySize, SMEMT_G);
    cudaFuncSetAttribute(gemm_m<1>, cudaFuncAttributeMaxDynamicSharedMemorySize, SMEMT_G);

    zero_counts_kernel<<<1, 32>>>();
    router_kernel<<<T_TOK, 128>>>(x, gw);

    {
        int n8;
        n8 = (int)((size_t)T_TOK * HDIM / 8);
        cvt_kernel<0><<<(n8 + 255) / 256, 256>>>(x, n8);
        n8 = (int)((size_t)NEXP * GU2 * HDIM / 8);
        cvt_kernel<1><<<(n8 + 255) / 256, 256>>>(wgu, n8);
        n8 = (int)((size_t)NEXP * HDIM * IDIM / 8);
        cvt_kernel<2><<<(n8 + 255) / 256, 256>>>(wdown, n8);
        n8 = (int)((size_t)SGU2 * HDIM / 8);
        cvt_kernel<3><<<(n8 + 255) / 256, 256>>>(sgu, n8);
        n8 = (int)((size_t)HDIM * SIDIM / 8);
        cvt_kernel<4><<<(n8 + 255) / 256, 256>>>(sdown, n8);
    }

    // merged GU GEMM: z<16 routed (y<22 used), z==16 shared (y<44)
    gemm_m<0><<<dim3(T_TOK / BM, SGU2 / BN, NEXP + 1), 128, SMEMT_G>>>(nullptr);
    // activations
    act_routed_kernel<<<dim3(512, NEXP), 256>>>();
    act_shared_kernel<<<T_TOK, 256>>>();
    // merged DOWN GEMM: z<16 routed, z==16 shared+combine
    gemm_m<1><<<dim3(T_TOK / BM, HDIM / BN, NEXP + 1), 128, SMEMT_G>>>(out);
}